// round 11
// baseline (speedup 1.0000x reference)
#include <cuda_runtime.h>
#include <cuda_fp16.h>
#include <math.h>

// CroquetGNN: 2-layer GCN, N=100000, E=3200000, feat 3 -> 16 -> 1
// out = sigmoid( GCNConv2( relu( GCNConv1(x) ) ) )
// GCNConv(x) = dinv[d] * segsum_{s->d}( dinv[s]*x[s] ) @ W (+ self loop + b)
//
// Pull-mode padded CSR. Layer1: 8-lane segments, random float4 gathers (at the
// L1tex sector-replay floor). Layer2: the ENTIRE gd table (fp16, 200KB) is
// staged in each CTA's shared memory, so gathers are LDS ops with no L1tex
// sector replays at all.

#define MAXN 100000
#define CAP 128          // padded row capacity (deg~Poisson(32))
#define TB 256
#define SPN 8            // lanes per node segment
#define L2_THREADS 1024
#define GD_SMEM_BYTES (MAXN * 2)   // 200000 B fp16 table (MAXN multiple of 8)

// ---- scratch (static device globals, BSS-zeroed at load; no allocation) ----
__device__ int    g_cnt[MAXN];        // degree counter (reset in k_layer2)
__device__ int    g_csr[MAXN * CAP];  // padded adjacency: src lists per dst
__device__ float  g_dinv[MAXN];       // rsqrt(deg+1)
__device__ float4 g_xd[MAXN];         // dinv[i] * x[i] (padded)
__device__ __half g_gdh[MAXN];        // fp16 gd = dinv[i]*(relu(conv1).W2)

// per-block dtype detect from INPUT only: int64 LE with values < 2^31 has zero hi words
__device__ __forceinline__ int detect64_block(const int* __restrict__ idx) {
    __shared__ int s64;
    if (threadIdx.x < 32) {
        int hi = __ldg(&idx[2 * threadIdx.x + 1]);
        unsigned m = __ballot_sync(0xFFFFFFFFu, hi == 0);
        if (threadIdx.x == 0) s64 = (m == 0xFFFFFFFFu);
    }
    __syncthreads();
    return s64;
}

// ---- k_scatter: one pass — count degree AND build padded CSR ----
__global__ void __launch_bounds__(TB) k_scatter(const int* __restrict__ idx, int E) {
    int is64 = detect64_block(idx);
    int e = blockIdx.x * TB + threadIdx.x;
    if (e >= E) return;
    int s, d;
    if (is64) {
        const long long* __restrict__ p = (const long long*)idx;
        s = (int)__ldg(&p[e]);
        d = (int)__ldg(&p[E + e]);
    } else {
        s = __ldg(&idx[e]);
        d = __ldg(&idx[E + e]);
    }
    int pos = atomicAdd(&g_cnt[d], 1);
    if (pos < CAP) g_csr[d * CAP + pos] = s;   // guard: never corrupt neighbors
}

// ---- k_xd: dinv = rsqrt(deg+1); xd = dinv*x  (cnt kept; layers read it) ----
__global__ void __launch_bounds__(TB) k_xd(const float* __restrict__ x, int N) {
    int i = blockIdx.x * TB + threadIdx.x;
    if (i >= N) return;
    float di = rsqrtf((float)(g_cnt[i] + 1));   // +1 self loop
    g_dinv[i] = di;
    g_xd[i] = make_float4(x[3 * i] * di, x[3 * i + 1] * di, x[3 * i + 2] * di, 0.f);
}

// ---- k_layer1: 8-lane-segment pull + fused conv1 epilogue -> gd (fp16) ----
__global__ void __launch_bounds__(TB) k_layer1(const float* __restrict__ W1,
                                               const float* __restrict__ b1,
                                               const float* __restrict__ W2, int N) {
    __shared__ float sW1[48], sb1[16], sW2[16];
    int t = threadIdx.x;
    if (t < 48) sW1[t] = __ldg(&W1[t]);
    if (t < 16) { sb1[t] = __ldg(&b1[t]); sW2[t] = __ldg(&W2[t]); }
    __syncthreads();

    int lane8 = t & (SPN - 1);
    int node = (blockIdx.x * TB + t) / SPN;
    bool valid = (node < N);
    int nd = valid ? node : 0;

    int deg = valid ? min(g_cnt[nd], CAP) : 0;
    const int* __restrict__ row = &g_csr[nd * CAP];
    float a0 = 0.f, a1 = 0.f, a2 = 0.f;
    int j = lane8;
    for (; j + 3 * SPN < deg; j += 4 * SPN) {
        int s0 = row[j], s1 = row[j + SPN], s2 = row[j + 2 * SPN], s3 = row[j + 3 * SPN];
        float4 v0 = g_xd[s0];
        float4 v1 = g_xd[s1];
        float4 v2 = g_xd[s2];
        float4 v3 = g_xd[s3];
        a0 += (v0.x + v1.x) + (v2.x + v3.x);
        a1 += (v0.y + v1.y) + (v2.y + v3.y);
        a2 += (v0.z + v1.z) + (v2.z + v3.z);
    }
    for (; j < deg; j += SPN) {
        float4 v = g_xd[row[j]];
        a0 += v.x; a1 += v.y; a2 += v.z;
    }
#pragma unroll
    for (int o = SPN / 2; o; o >>= 1) {
        a0 += __shfl_xor_sync(0xFFFFFFFFu, a0, o);
        a1 += __shfl_xor_sync(0xFFFFFFFFu, a1, o);
        a2 += __shfl_xor_sync(0xFFFFFFFFu, a2, o);
    }
    float di = valid ? g_dinv[nd] : 0.f;
    float4 xd = g_xd[nd];
    // self-loop contributes dinv^2 * x = dinv * xd
    float v0 = di * (a0 + xd.x);
    float v1 = di * (a1 + xd.y);
    float v2 = di * (a2 + xd.z);
    // 16 hidden channels over 8 lanes: 2 per lane
    int c0 = lane8, c1 = lane8 + 8;
    float h0 = fmaf(v0, sW1[c0], fmaf(v1, sW1[16 + c0], fmaf(v2, sW1[32 + c0], sb1[c0])));
    float h1 = fmaf(v0, sW1[c1], fmaf(v1, sW1[16 + c1], fmaf(v2, sW1[32 + c1], sb1[c1])));
    float p = fmaxf(h0, 0.f) * sW2[c0] + fmaxf(h1, 0.f) * sW2[c1];
#pragma unroll
    for (int o = SPN / 2; o; o >>= 1) p += __shfl_xor_sync(0xFFFFFFFFu, p, o);
    if (valid && lane8 == 0) g_gdh[nd] = __float2half(p * di);
}

// ---- k_layer2: full gd table in smem (fp16); CSR pull via LDS; sigmoid; resets cnt ----
__global__ void __launch_bounds__(L2_THREADS) k_layer2(const float* __restrict__ b2,
                                                       float* __restrict__ out, int N) {
    extern __shared__ __half s_gd[];
    int t = threadIdx.x;

    // cooperative broadcast load of the whole fp16 gd table (vectorized 16B)
    {
        uint4* __restrict__ dst = (uint4*)s_gd;
        const uint4* __restrict__ src = (const uint4*)g_gdh;
        int nvec = (N + 7) / 8;   // 8 halves per uint4; MAXN is a multiple of 8
        for (int i = t; i < nvec; i += L2_THREADS) dst[i] = src[i];
    }
    __syncthreads();

    float bias2 = __ldg(&b2[0]);
    int per = (N + gridDim.x - 1) / gridDim.x;
    int begin = blockIdx.x * per;
    int end = min(begin + per, N);
    int lane8 = t & (SPN - 1);
    int seg = t / SPN;                      // 0..127 segments per CTA
    const int segs = L2_THREADS / SPN;

    for (int node = begin + seg; node < end; node += segs) {
        int deg = min(g_cnt[node], CAP);
        const int* __restrict__ row = &g_csr[node * CAP];
        float a = 0.f;
        for (int j = lane8; j < deg; j += SPN)
            a += __half2float(s_gd[row[j]]);   // LDS gather: no L1tex replays
#pragma unroll
        for (int o = SPN / 2; o; o >>= 1) a += __shfl_xor_sync(0xFFFFFFFFu, a, o);
        if (lane8 == 0) {
            g_cnt[node] = 0;                   // consumer reset for next replay
            float di = g_dinv[node];
            float s = di * (a + __half2float(s_gd[node])) + bias2;
            out[node] = 1.0f / (1.0f + expf(-s));
        }
    }
}

extern "C" void kernel_launch(void* const* d_in, const int* in_sizes, int n_in,
                              void* d_out, int out_size) {
    const float* x   = (const float*)d_in[0];
    const int*   idx = (const int*)d_in[1];   // int32 or int64 (device-detected)
    const float* W1  = (const float*)d_in[2];
    const float* b1  = (const float*)d_in[3];
    const float* W2  = (const float*)d_in[4];
    const float* b2  = (const float*)d_in[5];
    float* out = (float*)d_out;

    int N_ = in_sizes[0] / 3;   // 100000
    int E_ = in_sizes[1] / 2;   // 3200000

    int nb_e = (E_ + TB - 1) / TB;
    int nb_n = (N_ + TB - 1) / TB;
    int nb_s = (N_ * SPN + TB - 1) / TB;   // segment-per-node grid (layer1)

    int dev = 0, sms = 148;
    cudaGetDevice(&dev);
    cudaDeviceGetAttribute(&sms, cudaDevAttrMultiProcessorCount, dev);

    static int smem_set = 0;
    if (!smem_set) {
        cudaFuncSetAttribute((const void*)k_layer2,
                             cudaFuncAttributeMaxDynamicSharedMemorySize,
                             GD_SMEM_BYTES);
        smem_set = 1;
    }

    k_scatter<<<nb_e, TB>>>(idx, E_);
    k_xd    <<<nb_n, TB>>>(x, N_);
    k_layer1<<<nb_s, TB>>>(W1, b1, W2, N_);
    k_layer2<<<sms, L2_THREADS, GD_SMEM_BYTES>>>(b2, out, N_);
}